// round 9
// baseline (speedup 1.0000x reference)
#include <cuda_runtime.h>
#include <math.h>
#include <cstdint>

#define NTOK 8192
#define DDIM 1024
#define HDIM 512
#define EEXP 6
#define FDIM 1536
#define LN_EPS 1e-5f

// ---------------- scratch (device globals) ----------------
__device__ float g_h[(size_t)NTOK * HDIM];
__device__ float g_xr[(size_t)NTOK * DDIM];            // rna-rounded x
__device__ float g_r1wt[(size_t)HDIM * DDIM];          // r1_w^T rounded  [H][D]
__device__ float g_w1t[(size_t)EEXP * FDIM * DDIM];    // W1^T rounded    [E][F][D]
__device__ float g_w2t[(size_t)EEXP * DDIM * FDIM];    // W2^T rounded    [E][D][F]
__device__ int   g_counts[EEXP];
__device__ int   g_lists[(size_t)EEXP * NTOK];
__device__ int   g_as_e[NTOK * 2];
__device__ int   g_as_s[NTOK * 2];
__device__ float g_as_w[NTOK * 2];
__device__ float g_act[(size_t)EEXP * NTOK * FDIM];
__device__ float g_y[(size_t)EEXP * NTOK * DDIM];

__device__ __forceinline__ float gelu_exact(float x) {
    return 0.5f * x * (1.0f + erff(x * 0.70710678118654752440f));
}
__device__ __forceinline__ float silu(float x) {
    return x / (1.0f + expf(-x));
}
__device__ __forceinline__ float rna_tf32(float f) {
    uint32_t r;
    asm("cvt.rna.tf32.f32 %0, %1;" : "=r"(r) : "f"(f));
    return __uint_as_float(r);
}

__global__ void reset_kernel() {
    if (threadIdx.x < EEXP) g_counts[threadIdx.x] = 0;
}

__global__ __launch_bounds__(256) void round_kernel(
    const float* __restrict__ src, float* __restrict__ dst)
{
    size_t i = (size_t)blockIdx.x * 256 + threadIdx.x;
    const float4 v = ((const float4*)src)[i];
    ((float4*)dst)[i] = make_float4(rna_tf32(v.x), rna_tf32(v.y), rna_tf32(v.z), rna_tf32(v.w));
}

// transpose [R,C] -> [C,R] with rna rounding; batched over z
__global__ __launch_bounds__(256) void transpose_rna_kernel(
    const float* __restrict__ src, float* __restrict__ dst, int R, int C)
{
    __shared__ float tile[32][33];
    const int e = blockIdx.z;
    src += (size_t)e * R * C;
    dst += (size_t)e * R * C;
    const int c0 = blockIdx.x * 32, r0 = blockIdx.y * 32;
    const int tx = threadIdx.x & 31, ty = threadIdx.x >> 5;
#pragma unroll
    for (int i = ty; i < 32; i += 8)
        tile[i][tx] = src[(size_t)(r0 + i) * C + c0 + tx];
    __syncthreads();
#pragma unroll
    for (int i = ty; i < 32; i += 8)
        dst[(size_t)(c0 + i) * R + r0 + tx] = rna_tf32(tile[tx][i]);
}

// ============================================================================
// TF32 tensor GEMM: 128(M) x 128(N) x 16(K) tiles, 8 warps (4Mx2N), 32x64/warp.
// 3-stage cp.async ring in dynamic smem, ONE __syncthreads per k-tile.
// A: [rows][K] row-major (pre-rounded, gather via lists). Bt: [Nn][K] row-major.
// ============================================================================
#define TBM 128
#define TBN 128
#define TBK 16
#define TS 20                                   // padded stride (floats)
#define A_FLOATS (TBM * TS)                     // 2560
#define B_FLOATS (TBN * TS)                     // 2560
#define STAGE_BYTES ((A_FLOATS + B_FLOATS) * 4) // 20480
#define NSTAGE 3
#define TG_SMEM (NSTAGE * STAGE_BYTES)          // 61440

__device__ __forceinline__ void mma_tf32(float* c, const uint32_t* a, const uint32_t* b) {
    asm volatile(
        "mma.sync.aligned.m16n8k8.row.col.f32.tf32.tf32.f32 "
        "{%0,%1,%2,%3}, {%4,%5,%6,%7}, {%8,%9}, {%0,%1,%2,%3};"
        : "+f"(c[0]), "+f"(c[1]), "+f"(c[2]), "+f"(c[3])
        : "r"(a[0]), "r"(a[1]), "r"(a[2]), "r"(a[3]), "r"(b[0]), "r"(b[1]));
}
__device__ __forceinline__ void ldsm_x4(uint32_t* r, uint32_t addr) {
    asm volatile("ldmatrix.sync.aligned.m8n8.x4.shared.b16 {%0,%1,%2,%3}, [%4];"
                 : "=r"(r[0]), "=r"(r[1]), "=r"(r[2]), "=r"(r[3]) : "r"(addr));
}
__device__ __forceinline__ void cp_async16(uint32_t dst_smem, const void* src, int src_bytes) {
    asm volatile("cp.async.cg.shared.global [%0], [%1], 16, %2;"
                 :: "r"(dst_smem), "l"(src), "r"(src_bytes));
}
__device__ __forceinline__ void cp_commit() { asm volatile("cp.async.commit_group;"); }
__device__ __forceinline__ void cp_wait0() { asm volatile("cp.async.wait_group 0;"); }
__device__ __forceinline__ void cp_wait1() { asm volatile("cp.async.wait_group 1;"); }

extern __shared__ __align__(128) char tg_dyn[];

__global__ __launch_bounds__(256, 2) void tgemm_kernel(
    const float* __restrict__ A, const float* __restrict__ Bt,
    const float* __restrict__ bias, float* __restrict__ C,
    const int* __restrict__ lists, const int* __restrict__ counts,
    int Mfull, int K, int Nn, int lda, size_t a_estride, int act_sel)
{
    const int e = blockIdx.y;
    const int Mcur = counts ? counts[e] : Mfull;
    const int m0 = blockIdx.x * TBM;
    if (m0 >= Mcur) return;
    const int n0 = blockIdx.z * TBN;

    const float* Ap    = A + (size_t)e * a_estride;
    const float* Btp   = Bt + (size_t)e * (size_t)K * Nn;
    const float* biasp = bias + (size_t)e * Nn;
    float*       Cp    = C + (size_t)e * (size_t)Mfull * Nn;
    const int*   list  = lists ? (lists + (size_t)e * Mfull) : nullptr;

    const int tid  = threadIdx.x;
    const int lane = tid & 31;
    const int warp = tid >> 5;
    const int warpM = warp >> 1;   // 0..3 -> *32 rows
    const int warpN = warp & 1;    // 0..1 -> *64 cols

    // ---- load mapping: 512 16B-chunks per operand per stage; 2 chunks/thread
    const int r0i = tid >> 2;              // rows r0i and r0i+64
    const int kq  = (tid & 3) * 4;         // float offset in k
    const bool av0 = (m0 + r0i) < Mcur;
    const bool av1 = (m0 + r0i + 64) < Mcur;
    const int tok0 = av0 ? (list ? list[m0 + r0i] : (m0 + r0i)) : 0;
    const int tok1 = av1 ? (list ? list[m0 + r0i + 64] : (m0 + r0i + 64)) : 0;
    const float* a_src0 = Ap + (size_t)tok0 * lda + kq;
    const float* a_src1 = Ap + (size_t)tok1 * lda + kq;
    const int ab0 = av0 ? 16 : 0, ab1 = av1 ? 16 : 0;
    const float* b_src0 = Btp + (size_t)(n0 + r0i) * K + kq;
    const float* b_src1 = Btp + (size_t)(n0 + r0i + 64) * K + kq;

    const uint32_t dynb = (uint32_t)__cvta_generic_to_shared(tg_dyn);
    const uint32_t a_d0 = (uint32_t)(r0i * TS + kq) * 4;
    const uint32_t a_d1 = (uint32_t)((r0i + 64) * TS + kq) * 4;
    const uint32_t b_d0 = (uint32_t)(A_FLOATS + r0i * TS + kq) * 4;
    const uint32_t b_d1 = (uint32_t)(A_FLOATS + (r0i + 64) * TS + kq) * 4;

    // ---- ldmatrix per-lane offsets
    const int lmA_r = (lane & 7) + ((lane >> 3) & 1) * 8;
    const int lmA_c = ((lane >> 4) & 1) * 4;
    const int lmB_r = (lane & 7) + ((lane >> 4) & 1) * 8;
    const int lmB_c = ((lane >> 3) & 1) * 4;

    float acc[2][8][4];
#pragma unroll
    for (int i = 0; i < 2; i++)
#pragma unroll
        for (int j = 0; j < 8; j++)
#pragma unroll
            for (int r = 0; r < 4; r++) acc[i][j][r] = 0.0f;

    const int T = K / TBK;

    // prefetch tiles 0,1 into stages 0,1
#pragma unroll
    for (int p = 0; p < 2; p++) {
        if (p < T) {
            const int k0 = p * TBK;
            const uint32_t sb = dynb + p * STAGE_BYTES;
            cp_async16(sb + a_d0, a_src0 + k0, ab0);
            cp_async16(sb + a_d1, a_src1 + k0, ab1);
            cp_async16(sb + b_d0, b_src0 + k0, 16);
            cp_async16(sb + b_d1, b_src1 + k0, 16);
            cp_commit();
        }
    }

    for (int t = 0; t < T; t++) {
        if (t < T - 1) cp_wait1(); else cp_wait0();
        __syncthreads();   // all warps finished iter t-1 => stage (t+2)%3 reusable

        if (t + 2 < T) {
            const int k0 = (t + 2) * TBK;
            const uint32_t sb = dynb + ((t + 2) % NSTAGE) * STAGE_BYTES;
            cp_async16(sb + a_d0, a_src0 + k0, ab0);
            cp_async16(sb + a_d1, a_src1 + k0, ab1);
            cp_async16(sb + b_d0, b_src0 + k0, 16);
            cp_async16(sb + b_d1, b_src1 + k0, 16);
            cp_commit();
        }

        const uint32_t abuf = dynb + (t % NSTAGE) * STAGE_BYTES;
        const uint32_t bbuf = abuf + A_FLOATS * 4;
#pragma unroll
        for (int kk = 0; kk < TBK; kk += 8) {
            uint32_t bfrag[8][2];
#pragma unroll
            for (int j = 0; j < 4; j++) {
                uint32_t addr = bbuf + ((warpN * 64 + j * 16 + lmB_r) * TS + kk + lmB_c) * 4;
                uint32_t r4[4];
                ldsm_x4(r4, addr);
                bfrag[2 * j][0] = r4[0]; bfrag[2 * j][1] = r4[1];
                bfrag[2 * j + 1][0] = r4[2]; bfrag[2 * j + 1][1] = r4[3];
            }
#pragma unroll
            for (int mi = 0; mi < 2; mi++) {
                uint32_t afrag[4];
                uint32_t addr = abuf + ((warpM * 32 + mi * 16 + lmA_r) * TS + kk + lmA_c) * 4;
                ldsm_x4(afrag, addr);
#pragma unroll
                for (int ni = 0; ni < 8; ni++)
                    mma_tf32(acc[mi][ni], afrag, bfrag[ni]);
            }
        }
    }
    // NOTE: no tail sync needed; epilogue reads only registers.

    const bool even_e = ((e & 1) == 0);
#pragma unroll
    for (int mi = 0; mi < 2; mi++) {
        int mbase = m0 + warpM * 32 + mi * 16 + (lane >> 2);
#pragma unroll
        for (int ni = 0; ni < 8; ni++) {
            int n = n0 + warpN * 64 + ni * 8 + 2 * (lane & 3);
            float bn0 = biasp[n], bn1 = biasp[n + 1];
            if (mbase < Mcur) {
                float v0 = acc[mi][ni][0] + bn0;
                float v1 = acc[mi][ni][1] + bn1;
                if (act_sel == 1) {
                    v0 = even_e ? gelu_exact(v0) : silu(v0);
                    v1 = even_e ? gelu_exact(v1) : silu(v1);
                    v0 = rna_tf32(v0); v1 = rna_tf32(v1);
                }
                *(float2*)&Cp[(size_t)mbase * Nn + n] = make_float2(v0, v1);
            }
            if (mbase + 8 < Mcur) {
                float v2 = acc[mi][ni][2] + bn0;
                float v3 = acc[mi][ni][3] + bn1;
                if (act_sel == 1) {
                    v2 = even_e ? gelu_exact(v2) : silu(v2);
                    v3 = even_e ? gelu_exact(v3) : silu(v3);
                    v2 = rna_tf32(v2); v3 = rna_tf32(v3);
                }
                *(float2*)&Cp[(size_t)(mbase + 8) * Nn + n] = make_float2(v2, v3);
            }
        }
    }
}

// ---------------- LayerNorm + exact GELU ----------------
__global__ __launch_bounds__(256) void ln_gelu_kernel(
    const float* __restrict__ ln_g, const float* __restrict__ ln_b)
{
    const int n = blockIdx.x;
    float* row = g_h + (size_t)n * HDIM;
    const int t = threadIdx.x;
    __shared__ float red[256];

    float v0 = row[t];
    float v1 = row[t + 256];
    red[t] = v0 + v1;
    __syncthreads();
    for (int s = 128; s > 0; s >>= 1) {
        if (t < s) red[t] += red[t + s];
        __syncthreads();
    }
    float mean = red[0] * (1.0f / HDIM);
    __syncthreads();

    float d0 = v0 - mean, d1 = v1 - mean;
    red[t] = d0 * d0 + d1 * d1;
    __syncthreads();
    for (int s = 128; s > 0; s >>= 1) {
        if (t < s) red[t] += red[t + s];
        __syncthreads();
    }
    float var = red[0] * (1.0f / HDIM);
    float inv = rsqrtf(var + LN_EPS);

    float o0 = d0 * inv * ln_g[t] + ln_b[t];
    float o1 = d1 * inv * ln_g[t + 256] + ln_b[t + 256];
    row[t]       = gelu_exact(o0);
    row[t + 256] = gelu_exact(o1);
}

// ---------------- router stage 2 (shuffle-reduced) ----------------
__global__ __launch_bounds__(128) void router2_kernel(
    const float* __restrict__ r2w, const float* __restrict__ r2b,
    const float* __restrict__ temp, const float* __restrict__ rbias)
{
    const int n = blockIdx.x;
    const int t = threadIdx.x;
    const int lane = t & 31, warp = t >> 5;
    const float* row = g_h + (size_t)n * HDIM;

    float acc[EEXP];
#pragma unroll
    for (int e = 0; e < EEXP; e++) acc[e] = 0.0f;
#pragma unroll
    for (int kk = 0; kk < HDIM / 128; kk++) {
        int k = t + kk * 128;
        float hv = row[k];
#pragma unroll
        for (int e = 0; e < EEXP; e++)
            acc[e] = fmaf(hv, r2w[k * EEXP + e], acc[e]);
    }
#pragma unroll
    for (int e = 0; e < EEXP; e++)
#pragma unroll
        for (int o = 16; o > 0; o >>= 1)
            acc[e] += __shfl_xor_sync(0xFFFFFFFF, acc[e], o);

    __shared__ float red[EEXP][4];
    if (lane == 0)
#pragma unroll
        for (int e = 0; e < EEXP; e++) red[e][warp] = acc[e];
    __syncthreads();

    if (t == 0) {
        float logits[EEXP];
        float tinv = 1.0f / temp[0];
#pragma unroll
        for (int e = 0; e < EEXP; e++)
            logits[e] = (red[e][0] + red[e][1] + red[e][2] + red[e][3] + r2b[e]) * tinv + rbias[e];

        float mx = logits[0];
#pragma unroll
        for (int e = 1; e < EEXP; e++) mx = fmaxf(mx, logits[e]);
        float p[EEXP], den = 0.0f;
#pragma unroll
        for (int e = 0; e < EEXP; e++) { p[e] = expf(logits[e] - mx); den += p[e]; }
        float inv = 1.0f / den;
#pragma unroll
        for (int e = 0; e < EEXP; e++) p[e] *= inv;

        int i0 = 0; float v0 = p[0];
#pragma unroll
        for (int e = 1; e < EEXP; e++) if (p[e] > v0) { v0 = p[e]; i0 = e; }
        int i1 = -1; float v1 = -1.0f;
#pragma unroll
        for (int e = 0; e < EEXP; e++) if (e != i0 && p[e] > v1) { v1 = p[e]; i1 = e; }

        int s0 = atomicAdd(&g_counts[i0], 1);
        int s1 = atomicAdd(&g_counts[i1], 1);
        g_lists[(size_t)i0 * NTOK + s0] = n;
        g_lists[(size_t)i1 * NTOK + s1] = n;
        g_as_e[2 * n] = i0; g_as_e[2 * n + 1] = i1;
        g_as_s[2 * n] = s0; g_as_s[2 * n + 1] = s1;
        g_as_w[2 * n] = v0; g_as_w[2 * n + 1] = v1;
    }
}

// ---------------- combine ----------------
__global__ __launch_bounds__(256) void combine_kernel(float* __restrict__ out)
{
    const int n = blockIdx.x;
    const int t = threadIdx.x;
    const int e0 = g_as_e[2 * n],   e1 = g_as_e[2 * n + 1];
    const int s0 = g_as_s[2 * n],   s1 = g_as_s[2 * n + 1];
    const float w0 = g_as_w[2 * n], w1 = g_as_w[2 * n + 1];
    const float4* y0 = (const float4*)(g_y + ((size_t)e0 * NTOK + s0) * DDIM);
    const float4* y1 = (const float4*)(g_y + ((size_t)e1 * NTOK + s1) * DDIM);
    float4* o = (float4*)(out + (size_t)n * DDIM);
    for (int d = t; d < DDIM / 4; d += 256) {
        float4 a = y0[d], b = y1[d];
        o[d] = make_float4(w0 * a.x + w1 * b.x, w0 * a.y + w1 * b.y,
                           w0 * a.z + w1 * b.z, w0 * a.w + w1 * b.w);
    }
}

// ---------------- launch ----------------
extern "C" void kernel_launch(void* const* d_in, const int* in_sizes, int n_in,
                              void* d_out, int out_size)
{
    const float* x      = (const float*)d_in[0];
    const float* r1_w   = (const float*)d_in[1];
    const float* r1_b   = (const float*)d_in[2];
    const float* ln_g   = (const float*)d_in[3];
    const float* ln_b   = (const float*)d_in[4];
    const float* r2_w   = (const float*)d_in[5];
    const float* r2_b   = (const float*)d_in[6];
    const float* temp   = (const float*)d_in[7];
    const float* rbias  = (const float*)d_in[8];
    const float* W1     = (const float*)d_in[9];
    const float* b1     = (const float*)d_in[10];
    const float* W2     = (const float*)d_in[11];
    const float* b2     = (const float*)d_in[12];
    float* out = (float*)d_out;

    void *p_h, *p_xr, *p_r1wt, *p_w1t, *p_w2t, *p_lists, *p_counts, *p_act, *p_y;
    cudaGetSymbolAddress(&p_h, g_h);
    cudaGetSymbolAddress(&p_xr, g_xr);
    cudaGetSymbolAddress(&p_r1wt, g_r1wt);
    cudaGetSymbolAddress(&p_w1t, g_w1t);
    cudaGetSymbolAddress(&p_w2t, g_w2t);
    cudaGetSymbolAddress(&p_lists, g_lists);
    cudaGetSymbolAddress(&p_counts, g_counts);
    cudaGetSymbolAddress(&p_act, g_act);
    cudaGetSymbolAddress(&p_y, g_y);

    cudaFuncSetAttribute(tgemm_kernel, cudaFuncAttributeMaxDynamicSharedMemorySize, TG_SMEM);

    reset_kernel<<<1, 32>>>();

    // prep: round x; transpose+round weights to [N][K]
    round_kernel<<<(NTOK * DDIM) / 1024, 256>>>(x, (float*)p_xr);
    {
        dim3 b(256);
        transpose_rna_kernel<<<dim3(HDIM / 32, DDIM / 32, 1), b>>>(r1_w, (float*)p_r1wt, DDIM, HDIM);
        transpose_rna_kernel<<<dim3(FDIM / 32, DDIM / 32, EEXP), b>>>(W1, (float*)p_w1t, DDIM, FDIM);
        transpose_rna_kernel<<<dim3(DDIM / 32, FDIM / 32, EEXP), b>>>(W2, (float*)p_w2t, FDIM, DDIM);
    }

    // Router GEMM1 (tf32 tensor): h = x @ r1_w + r1_b
    {
        dim3 grid(NTOK / TBM, 1, HDIM / TBN);
        tgemm_kernel<<<grid, 256, TG_SMEM>>>((const float*)p_xr, (const float*)p_r1wt, r1_b,
                                             (float*)p_h, nullptr, nullptr,
                                             NTOK, DDIM, HDIM, DDIM, 0, 0);
    }

    ln_gelu_kernel<<<NTOK, 256>>>(ln_g, ln_b);
    router2_kernel<<<NTOK, 128>>>(r2_w, r2_b, temp, rbias);

    // Expert GEMM1: act = rna(actfn(x[gather] @ W1[e] + b1[e]))
    {
        dim3 grid(NTOK / TBM, EEXP, FDIM / TBN);
        tgemm_kernel<<<grid, 256, TG_SMEM>>>((const float*)p_xr, (const float*)p_w1t, b1,
                                             (float*)p_act, (const int*)p_lists, (const int*)p_counts,
                                             NTOK, DDIM, FDIM, DDIM, 0, 1);
    }

    // Expert GEMM2: y = act @ W2[e] + b2[e]
    {
        dim3 grid(NTOK / TBM, EEXP, DDIM / TBN);
        tgemm_kernel<<<grid, 256, TG_SMEM>>>((const float*)p_act, (const float*)p_w2t, b2,
                                             (float*)p_y, nullptr, (const int*)p_counts,
                                             NTOK, FDIM, DDIM, FDIM,
                                             (size_t)NTOK * FDIM, 0);
    }

    combine_kernel<<<NTOK, 256>>>(out);
}

// round 11
// speedup vs baseline: 1.2521x; 1.2521x over previous
#include <cuda_runtime.h>
#include <math.h>
#include <cstdint>

#define NTOK 8192
#define DDIM 1024
#define HDIM 512
#define EEXP 6
#define FDIM 1536
#define LN_EPS 1e-5f

// ---------------- scratch (device globals) ----------------
__device__ float g_h[(size_t)NTOK * HDIM];
__device__ float g_xr[(size_t)NTOK * DDIM];            // rna-rounded x
__device__ float g_r1wt[(size_t)HDIM * DDIM];          // r1_w^T rounded  [H][D]
__device__ float g_w1t[(size_t)EEXP * FDIM * DDIM];    // W1^T rounded    [E][F][D]
__device__ float g_w2t[(size_t)EEXP * DDIM * FDIM];    // W2^T rounded    [E][D][F]
__device__ int   g_counts[EEXP];
__device__ int   g_lists[(size_t)EEXP * NTOK];
__device__ int   g_as_e[NTOK * 2];
__device__ int   g_as_s[NTOK * 2];
__device__ float g_as_w[NTOK * 2];
__device__ float g_act[(size_t)EEXP * NTOK * FDIM];
__device__ float g_y[(size_t)EEXP * NTOK * DDIM];

__device__ __forceinline__ float gelu_exact(float x) {
    return 0.5f * x * (1.0f + erff(x * 0.70710678118654752440f));
}
__device__ __forceinline__ float silu(float x) {
    return x / (1.0f + expf(-x));
}
__device__ __forceinline__ float rna_tf32(float f) {
    uint32_t r;
    asm("cvt.rna.tf32.f32 %0, %1;" : "=r"(r) : "f"(f));
    return __uint_as_float(r);
}

__global__ void reset_kernel() {
    if (threadIdx.x < EEXP) g_counts[threadIdx.x] = 0;
}

__global__ __launch_bounds__(256) void round_kernel(
    const float* __restrict__ src, float* __restrict__ dst)
{
    size_t i = (size_t)blockIdx.x * 256 + threadIdx.x;
    const float4 v = ((const float4*)src)[i];
    ((float4*)dst)[i] = make_float4(rna_tf32(v.x), rna_tf32(v.y), rna_tf32(v.z), rna_tf32(v.w));
}

// transpose [R,C] -> [C,R] with rna rounding; batched over z
__global__ __launch_bounds__(256) void transpose_rna_kernel(
    const float* __restrict__ src, float* __restrict__ dst, int R, int C)
{
    __shared__ float tile[32][33];
    const int e = blockIdx.z;
    src += (size_t)e * R * C;
    dst += (size_t)e * R * C;
    const int c0 = blockIdx.x * 32, r0 = blockIdx.y * 32;
    const int tx = threadIdx.x & 31, ty = threadIdx.x >> 5;
#pragma unroll
    for (int i = ty; i < 32; i += 8)
        tile[i][tx] = src[(size_t)(r0 + i) * C + c0 + tx];
    __syncthreads();
#pragma unroll
    for (int i = ty; i < 32; i += 8)
        dst[(size_t)(c0 + i) * R + r0 + tx] = rna_tf32(tile[tx][i]);
}

// ============================================================================
// TF32 tensor GEMM: 128(M) x 256(N) x 16(K) block tile, 16 warps (4Mx4N),
// 32x64 per warp (identical warp shape to proven R5 config; 16 warps/SM).
// 2-stage cp.async double buffer in dynamic smem (R5's proven loop structure).
// A: [rows][K] row-major (pre-rounded, gather via lists). Bt: [Nn][K] row-major.
// ============================================================================
#define TBM 128
#define TBN 256
#define TBK 16
#define TS 20                                   // padded stride (floats)
#define A_FLOATS (TBM * TS)                     // 2560
#define B_FLOATS (TBN * TS)                     // 5120
#define STAGE_BYTES ((A_FLOATS + B_FLOATS) * 4) // 30720
#define TG_SMEM (2 * STAGE_BYTES)               // 61440

__device__ __forceinline__ void mma_tf32(float* c, const uint32_t* a, const uint32_t* b) {
    asm volatile(
        "mma.sync.aligned.m16n8k8.row.col.f32.tf32.tf32.f32 "
        "{%0,%1,%2,%3}, {%4,%5,%6,%7}, {%8,%9}, {%0,%1,%2,%3};"
        : "+f"(c[0]), "+f"(c[1]), "+f"(c[2]), "+f"(c[3])
        : "r"(a[0]), "r"(a[1]), "r"(a[2]), "r"(a[3]), "r"(b[0]), "r"(b[1]));
}
__device__ __forceinline__ void ldsm_x4(uint32_t* r, uint32_t addr) {
    asm volatile("ldmatrix.sync.aligned.m8n8.x4.shared.b16 {%0,%1,%2,%3}, [%4];"
                 : "=r"(r[0]), "=r"(r[1]), "=r"(r[2]), "=r"(r[3]) : "r"(addr));
}
__device__ __forceinline__ void cp_async16(uint32_t dst_smem, const void* src, int src_bytes) {
    asm volatile("cp.async.cg.shared.global [%0], [%1], 16, %2;"
                 :: "r"(dst_smem), "l"(src), "r"(src_bytes));
}
__device__ __forceinline__ void cp_commit() { asm volatile("cp.async.commit_group;"); }
__device__ __forceinline__ void cp_wait0() { asm volatile("cp.async.wait_group 0;"); }

extern __shared__ __align__(128) char tg_dyn[];

__global__ __launch_bounds__(512, 1) void tgemm_kernel(
    const float* __restrict__ A, const float* __restrict__ Bt,
    const float* __restrict__ bias, float* __restrict__ C,
    const int* __restrict__ lists, const int* __restrict__ counts,
    int Mfull, int K, int Nn, int lda, size_t a_estride, int act_sel)
{
    const int e = blockIdx.y;
    const int Mcur = counts ? counts[e] : Mfull;
    const int m0 = blockIdx.x * TBM;
    if (m0 >= Mcur) return;
    const int n0 = blockIdx.z * TBN;

    const float* Ap    = A + (size_t)e * a_estride;
    const float* Btp   = Bt + (size_t)e * (size_t)K * Nn;
    const float* biasp = bias + (size_t)e * Nn;
    float*       Cp    = C + (size_t)e * (size_t)Mfull * Nn;
    const int*   list  = lists ? (lists + (size_t)e * Mfull) : nullptr;

    const int tid  = threadIdx.x;
    const int lane = tid & 31;
    const int warp = tid >> 5;
    const int warpM = warp >> 2;   // 0..3 -> *32 rows
    const int warpN = warp & 3;    // 0..3 -> *64 cols

    // ---- load mapping per stage: A 512 chunks (1/thread), B 1024 chunks (2/thread)
    const int arow = tid >> 2;             // 0..127
    const int kq   = (tid & 3) * 4;        // float offset in k
    const bool avld = (m0 + arow) < Mcur;
    const int  atok = avld ? (list ? list[m0 + arow] : (m0 + arow)) : 0;
    const float* a_src = Ap + (size_t)atok * lda + kq;
    const int ab = avld ? 16 : 0;
    // B rows arow and arow+128
    const float* b_src0 = Btp + (size_t)(n0 + arow) * K + kq;
    const float* b_src1 = Btp + (size_t)(n0 + arow + 128) * K + kq;

    const uint32_t dynb = (uint32_t)__cvta_generic_to_shared(tg_dyn);
    const uint32_t a_d  = (uint32_t)(arow * TS + kq) * 4;
    const uint32_t b_d0 = (uint32_t)(A_FLOATS + arow * TS + kq) * 4;
    const uint32_t b_d1 = (uint32_t)(A_FLOATS + (arow + 128) * TS + kq) * 4;

    // ---- ldmatrix per-lane offsets (identical to proven config)
    const int lmA_r = (lane & 7) + ((lane >> 3) & 1) * 8;
    const int lmA_c = ((lane >> 4) & 1) * 4;
    const int lmB_r = (lane & 7) + ((lane >> 4) & 1) * 8;
    const int lmB_c = ((lane >> 3) & 1) * 4;

    float acc[2][8][4];
#pragma unroll
    for (int i = 0; i < 2; i++)
#pragma unroll
        for (int j = 0; j < 8; j++)
#pragma unroll
            for (int r = 0; r < 4; r++) acc[i][j][r] = 0.0f;

    const int T = K / TBK;

    // prefetch tile 0 -> stage 0
    cp_async16(dynb + a_d, a_src, ab);
    cp_async16(dynb + b_d0, b_src0, 16);
    cp_async16(dynb + b_d1, b_src1, 16);
    cp_commit();

    for (int t = 0; t < T; t++) {
        cp_wait0();
        __syncthreads();

        if (t + 1 < T) {
            const int k0 = (t + 1) * TBK;
            const uint32_t sb = dynb + ((t + 1) & 1) * STAGE_BYTES;
            cp_async16(sb + a_d, a_src + k0, ab);
            cp_async16(sb + b_d0, b_src0 + k0, 16);
            cp_async16(sb + b_d1, b_src1 + k0, 16);
            cp_commit();
        }

        const uint32_t abuf = dynb + (t & 1) * STAGE_BYTES;
        const uint32_t bbuf = abuf + A_FLOATS * 4;
#pragma unroll
        for (int kk = 0; kk < TBK; kk += 8) {
            uint32_t bfrag[8][2];
#pragma unroll
            for (int j = 0; j < 4; j++) {
                uint32_t addr = bbuf + ((warpN * 64 + j * 16 + lmB_r) * TS + kk + lmB_c) * 4;
                uint32_t r4[4];
                ldsm_x4(r4, addr);
                bfrag[2 * j][0] = r4[0]; bfrag[2 * j][1] = r4[1];
                bfrag[2 * j + 1][0] = r4[2]; bfrag[2 * j + 1][1] = r4[3];
            }
#pragma unroll
            for (int mi = 0; mi < 2; mi++) {
                uint32_t afrag[4];
                uint32_t addr = abuf + ((warpM * 32 + mi * 16 + lmA_r) * TS + kk + lmA_c) * 4;
                ldsm_x4(afrag, addr);
#pragma unroll
                for (int ni = 0; ni < 8; ni++)
                    mma_tf32(acc[mi][ni], afrag, bfrag[ni]);
            }
        }
        __syncthreads();
    }

    const bool even_e = ((e & 1) == 0);
#pragma unroll
    for (int mi = 0; mi < 2; mi++) {
        int mbase = m0 + warpM * 32 + mi * 16 + (lane >> 2);
#pragma unroll
        for (int ni = 0; ni < 8; ni++) {
            int n = n0 + warpN * 64 + ni * 8 + 2 * (lane & 3);
            float bn0 = biasp[n], bn1 = biasp[n + 1];
            if (mbase < Mcur) {
                float v0 = acc[mi][ni][0] + bn0;
                float v1 = acc[mi][ni][1] + bn1;
                if (act_sel == 1) {
                    v0 = even_e ? gelu_exact(v0) : silu(v0);
                    v1 = even_e ? gelu_exact(v1) : silu(v1);
                    v0 = rna_tf32(v0); v1 = rna_tf32(v1);
                }
                *(float2*)&Cp[(size_t)mbase * Nn + n] = make_float2(v0, v1);
            }
            if (mbase + 8 < Mcur) {
                float v2 = acc[mi][ni][2] + bn0;
                float v3 = acc[mi][ni][3] + bn1;
                if (act_sel == 1) {
                    v2 = even_e ? gelu_exact(v2) : silu(v2);
                    v3 = even_e ? gelu_exact(v3) : silu(v3);
                    v2 = rna_tf32(v2); v3 = rna_tf32(v3);
                }
                *(float2*)&Cp[(size_t)(mbase + 8) * Nn + n] = make_float2(v2, v3);
            }
        }
    }
}

// ---------------- LayerNorm + exact GELU ----------------
__global__ __launch_bounds__(256) void ln_gelu_kernel(
    const float* __restrict__ ln_g, const float* __restrict__ ln_b)
{
    const int n = blockIdx.x;
    float* row = g_h + (size_t)n * HDIM;
    const int t = threadIdx.x;
    __shared__ float red[256];

    float v0 = row[t];
    float v1 = row[t + 256];
    red[t] = v0 + v1;
    __syncthreads();
    for (int s = 128; s > 0; s >>= 1) {
        if (t < s) red[t] += red[t + s];
        __syncthreads();
    }
    float mean = red[0] * (1.0f / HDIM);
    __syncthreads();

    float d0 = v0 - mean, d1 = v1 - mean;
    red[t] = d0 * d0 + d1 * d1;
    __syncthreads();
    for (int s = 128; s > 0; s >>= 1) {
        if (t < s) red[t] += red[t + s];
        __syncthreads();
    }
    float var = red[0] * (1.0f / HDIM);
    float inv = rsqrtf(var + LN_EPS);

    float o0 = d0 * inv * ln_g[t] + ln_b[t];
    float o1 = d1 * inv * ln_g[t + 256] + ln_b[t + 256];
    row[t]       = gelu_exact(o0);
    row[t + 256] = gelu_exact(o1);
}

// ---------------- router stage 2 (shuffle-reduced) ----------------
__global__ __launch_bounds__(128) void router2_kernel(
    const float* __restrict__ r2w, const float* __restrict__ r2b,
    const float* __restrict__ temp, const float* __restrict__ rbias)
{
    const int n = blockIdx.x;
    const int t = threadIdx.x;
    const int lane = t & 31, warp = t >> 5;
    const float* row = g_h + (size_t)n * HDIM;

    float acc[EEXP];
#pragma unroll
    for (int e = 0; e < EEXP; e++) acc[e] = 0.0f;
#pragma unroll
    for (int kk = 0; kk < HDIM / 128; kk++) {
        int k = t + kk * 128;
        float hv = row[k];
#pragma unroll
        for (int e = 0; e < EEXP; e++)
            acc[e] = fmaf(hv, r2w[k * EEXP + e], acc[e]);
    }
#pragma unroll
    for (int e = 0; e < EEXP; e++)
#pragma unroll
        for (int o = 16; o > 0; o >>= 1)
            acc[e] += __shfl_xor_sync(0xFFFFFFFF, acc[e], o);

    __shared__ float red[EEXP][4];
    if (lane == 0)
#pragma unroll
        for (int e = 0; e < EEXP; e++) red[e][warp] = acc[e];
    __syncthreads();

    if (t == 0) {
        float logits[EEXP];
        float tinv = 1.0f / temp[0];
#pragma unroll
        for (int e = 0; e < EEXP; e++)
            logits[e] = (red[e][0] + red[e][1] + red[e][2] + red[e][3] + r2b[e]) * tinv + rbias[e];

        float mx = logits[0];
#pragma unroll
        for (int e = 1; e < EEXP; e++) mx = fmaxf(mx, logits[e]);
        float p[EEXP], den = 0.0f;
#pragma unroll
        for (int e = 0; e < EEXP; e++) { p[e] = expf(logits[e] - mx); den += p[e]; }
        float inv = 1.0f / den;
#pragma unroll
        for (int e = 0; e < EEXP; e++) p[e] *= inv;

        int i0 = 0; float v0 = p[0];
#pragma unroll
        for (int e = 1; e < EEXP; e++) if (p[e] > v0) { v0 = p[e]; i0 = e; }
        int i1 = -1; float v1 = -1.0f;
#pragma unroll
        for (int e = 0; e < EEXP; e++) if (e != i0 && p[e] > v1) { v1 = p[e]; i1 = e; }

        int s0 = atomicAdd(&g_counts[i0], 1);
        int s1 = atomicAdd(&g_counts[i1], 1);
        g_lists[(size_t)i0 * NTOK + s0] = n;
        g_lists[(size_t)i1 * NTOK + s1] = n;
        g_as_e[2 * n] = i0; g_as_e[2 * n + 1] = i1;
        g_as_s[2 * n] = s0; g_as_s[2 * n + 1] = s1;
        g_as_w[2 * n] = v0; g_as_w[2 * n + 1] = v1;
    }
}

// ---------------- combine ----------------
__global__ __launch_bounds__(256) void combine_kernel(float* __restrict__ out)
{
    const int n = blockIdx.x;
    const int t = threadIdx.x;
    const int e0 = g_as_e[2 * n],   e1 = g_as_e[2 * n + 1];
    const int s0 = g_as_s[2 * n],   s1 = g_as_s[2 * n + 1];
    const float w0 = g_as_w[2 * n], w1 = g_as_w[2 * n + 1];
    const float4* y0 = (const float4*)(g_y + ((size_t)e0 * NTOK + s0) * DDIM);
    const float4* y1 = (const float4*)(g_y + ((size_t)e1 * NTOK + s1) * DDIM);
    float4* o = (float4*)(out + (size_t)n * DDIM);
    for (int d = t; d < DDIM / 4; d += 256) {
        float4 a = y0[d], b = y1[d];
        o[d] = make_float4(w0 * a.x + w1 * b.x, w0 * a.y + w1 * b.y,
                           w0 * a.z + w1 * b.z, w0 * a.w + w1 * b.w);
    }
}

// ---------------- launch ----------------
extern "C" void kernel_launch(void* const* d_in, const int* in_sizes, int n_in,
                              void* d_out, int out_size)
{
    const float* x      = (const float*)d_in[0];
    const float* r1_w   = (const float*)d_in[1];
    const float* r1_b   = (const float*)d_in[2];
    const float* ln_g   = (const float*)d_in[3];
    const float* ln_b   = (const float*)d_in[4];
    const float* r2_w   = (const float*)d_in[5];
    const float* r2_b   = (const float*)d_in[6];
    const float* temp   = (const float*)d_in[7];
    const float* rbias  = (const float*)d_in[8];
    const float* W1     = (const float*)d_in[9];
    const float* b1     = (const float*)d_in[10];
    const float* W2     = (const float*)d_in[11];
    const float* b2     = (const float*)d_in[12];
    float* out = (float*)d_out;

    void *p_h, *p_xr, *p_r1wt, *p_w1t, *p_w2t, *p_lists, *p_counts, *p_act, *p_y;
    cudaGetSymbolAddress(&p_h, g_h);
    cudaGetSymbolAddress(&p_xr, g_xr);
    cudaGetSymbolAddress(&p_r1wt, g_r1wt);
    cudaGetSymbolAddress(&p_w1t, g_w1t);
    cudaGetSymbolAddress(&p_w2t, g_w2t);
    cudaGetSymbolAddress(&p_lists, g_lists);
    cudaGetSymbolAddress(&p_counts, g_counts);
    cudaGetSymbolAddress(&p_act, g_act);
    cudaGetSymbolAddress(&p_y, g_y);

    cudaFuncSetAttribute(tgemm_kernel, cudaFuncAttributeMaxDynamicSharedMemorySize, TG_SMEM);

    reset_kernel<<<1, 32>>>();

    // prep: round x; transpose+round weights to [N][K]
    round_kernel<<<(NTOK * DDIM) / 1024, 256>>>(x, (float*)p_xr);
    {
        dim3 b(256);
        transpose_rna_kernel<<<dim3(HDIM / 32, DDIM / 32, 1), b>>>(r1_w, (float*)p_r1wt, DDIM, HDIM);
        transpose_rna_kernel<<<dim3(FDIM / 32, DDIM / 32, EEXP), b>>>(W1, (float*)p_w1t, DDIM, FDIM);
        transpose_rna_kernel<<<dim3(DDIM / 32, FDIM / 32, EEXP), b>>>(W2, (float*)p_w2t, FDIM, DDIM);
    }

    // Router GEMM1 (tf32 tensor): h = x @ r1_w + r1_b
    {
        dim3 grid(NTOK / TBM, 1, HDIM / TBN);
        tgemm_kernel<<<grid, 512, TG_SMEM>>>((const float*)p_xr, (const float*)p_r1wt, r1_b,
                                             (float*)p_h, nullptr, nullptr,
                                             NTOK, DDIM, HDIM, DDIM, 0, 0);
    }

    ln_gelu_kernel<<<NTOK, 256>>>(ln_g, ln_b);
    router2_kernel<<<NTOK, 128>>>(r2_w, r2_b, temp, rbias);

    // Expert GEMM1: act = rna(actfn(x[gather] @ W1[e] + b1[e]))
    {
        dim3 grid(NTOK / TBM, EEXP, FDIM / TBN);
        tgemm_kernel<<<grid, 512, TG_SMEM>>>((const float*)p_xr, (const float*)p_w1t, b1,
                                             (float*)p_act, (const int*)p_lists, (const int*)p_counts,
                                             NTOK, DDIM, FDIM, DDIM, 0, 1);
    }

    // Expert GEMM2: y = act @ W2[e] + b2[e]
    {
        dim3 grid(NTOK / TBM, EEXP, DDIM / TBN);
        tgemm_kernel<<<grid, 512, TG_SMEM>>>((const float*)p_act, (const float*)p_w2t, b2,
                                             (float*)p_y, nullptr, (const int*)p_counts,
                                             NTOK, FDIM, DDIM, FDIM,
                                             (size_t)NTOK * FDIM, 0);
    }

    combine_kernel<<<NTOK, 256>>>(out);
}

// round 15
// speedup vs baseline: 1.5905x; 1.2702x over previous
#include <cuda_runtime.h>
#include <math.h>
#include <cstdint>

#define NTOK 8192
#define DDIM 1024
#define HDIM 512
#define EEXP 6
#define FDIM 1536
#define LN_EPS 1e-5f

// ---------------- scratch (device globals) ----------------
__device__ float g_h[(size_t)NTOK * HDIM];
__device__ float g_xr[(size_t)NTOK * DDIM];            // rna-rounded x
__device__ float g_r1wt[(size_t)HDIM * DDIM];          // r1_w^T rounded  [H][D]
__device__ float g_w1t[(size_t)EEXP * FDIM * DDIM];    // W1^T rounded    [E][F][D]
__device__ float g_w2t[(size_t)EEXP * DDIM * FDIM];    // W2^T rounded    [E][D][F]
__device__ int   g_counts[EEXP];
__device__ int   g_lists[(size_t)EEXP * NTOK];
__device__ int   g_as_e[NTOK * 2];
__device__ int   g_as_s[NTOK * 2];
__device__ float g_as_w[NTOK * 2];
__device__ float g_act[(size_t)EEXP * NTOK * FDIM];
__device__ float g_y[(size_t)EEXP * NTOK * DDIM];

__device__ __forceinline__ float gelu_exact(float x) {
    return 0.5f * x * (1.0f + erff(x * 0.70710678118654752440f));
}
__device__ __forceinline__ float silu(float x) {
    return x / (1.0f + expf(-x));
}
__device__ __forceinline__ float rna_tf32(float f) {
    uint32_t r;
    asm("cvt.rna.tf32.f32 %0, %1;" : "=r"(r) : "f"(f));
    return __uint_as_float(r);
}

__global__ void reset_kernel() {
    if (threadIdx.x < EEXP) g_counts[threadIdx.x] = 0;
}

__global__ __launch_bounds__(256) void round_kernel(
    const float* __restrict__ src, float* __restrict__ dst)
{
    size_t i = (size_t)blockIdx.x * 256 + threadIdx.x;
    const float4 v = ((const float4*)src)[i];
    ((float4*)dst)[i] = make_float4(rna_tf32(v.x), rna_tf32(v.y), rna_tf32(v.z), rna_tf32(v.w));
}

// transpose [R,C] -> [C,R] with rna rounding; batched over z
__global__ __launch_bounds__(256) void transpose_rna_kernel(
    const float* __restrict__ src, float* __restrict__ dst, int R, int C)
{
    __shared__ float tile[32][33];
    const int e = blockIdx.z;
    src += (size_t)e * R * C;
    dst += (size_t)e * R * C;
    const int c0 = blockIdx.x * 32, r0 = blockIdx.y * 32;
    const int tx = threadIdx.x & 31, ty = threadIdx.x >> 5;
#pragma unroll
    for (int i = ty; i < 32; i += 8)
        tile[i][tx] = src[(size_t)(r0 + i) * C + c0 + tx];
    __syncthreads();
#pragma unroll
    for (int i = ty; i < 32; i += 8)
        dst[(size_t)(c0 + i) * R + r0 + tx] = rna_tf32(tile[tx][i]);
}

// ============================================================================
// TF32 tensor GEMM: 128(M) x 128(N) x 32(K) tiles, 8 warps (4Mx2N), 32x64/warp.
// PROVEN R5 structure (256 thr, 2 CTA/SM, 2-stage double buffer, 2 syncs/tile)
// with BK doubled 16->32: half the barriers, 4 k8-steps per sync.
// A: [rows][K] row-major (pre-rounded, gather via lists). Bt: [Nn][K] row-major.
// ============================================================================
#define TBM 128
#define TBN 128
#define TBK 32
#define TS 36                                   // padded stride: banks 4r mod 32 disjoint
#define A_FLOATS (TBM * TS)                     // 4608
#define B_FLOATS (TBN * TS)                     // 4608
#define STAGE_BYTES ((A_FLOATS + B_FLOATS) * 4) // 36864
#define TG_SMEM (2 * STAGE_BYTES)               // 73728

__device__ __forceinline__ void mma_tf32(float* c, const uint32_t* a, const uint32_t* b) {
    asm volatile(
        "mma.sync.aligned.m16n8k8.row.col.f32.tf32.tf32.f32 "
        "{%0,%1,%2,%3}, {%4,%5,%6,%7}, {%8,%9}, {%0,%1,%2,%3};"
        : "+f"(c[0]), "+f"(c[1]), "+f"(c[2]), "+f"(c[3])
        : "r"(a[0]), "r"(a[1]), "r"(a[2]), "r"(a[3]), "r"(b[0]), "r"(b[1]));
}
__device__ __forceinline__ void ldsm_x4(uint32_t* r, uint32_t addr) {
    asm volatile("ldmatrix.sync.aligned.m8n8.x4.shared.b16 {%0,%1,%2,%3}, [%4];"
                 : "=r"(r[0]), "=r"(r[1]), "=r"(r[2]), "=r"(r[3]) : "r"(addr));
}
__device__ __forceinline__ void cp_async16(uint32_t dst_smem, const void* src, int src_bytes) {
    asm volatile("cp.async.cg.shared.global [%0], [%1], 16, %2;"
                 :: "r"(dst_smem), "l"(src), "r"(src_bytes));
}
__device__ __forceinline__ void cp_commit() { asm volatile("cp.async.commit_group;"); }
__device__ __forceinline__ void cp_wait0() { asm volatile("cp.async.wait_group 0;"); }

extern __shared__ __align__(128) char tg_dyn[];

__global__ __launch_bounds__(256, 2) void tgemm_kernel(
    const float* __restrict__ A, const float* __restrict__ Bt,
    const float* __restrict__ bias, float* __restrict__ C,
    const int* __restrict__ lists, const int* __restrict__ counts,
    int Mfull, int K, int Nn, int lda, size_t a_estride, int act_sel)
{
    const int e = blockIdx.y;
    const int Mcur = counts ? counts[e] : Mfull;
    const int m0 = blockIdx.x * TBM;
    if (m0 >= Mcur) return;
    const int n0 = blockIdx.z * TBN;

    const float* Ap    = A + (size_t)e * a_estride;
    const float* Btp   = Bt + (size_t)e * (size_t)K * Nn;
    const float* biasp = bias + (size_t)e * Nn;
    float*       Cp    = C + (size_t)e * (size_t)Mfull * Nn;
    const int*   list  = lists ? (lists + (size_t)e * Mfull) : nullptr;

    const int tid  = threadIdx.x;
    const int lane = tid & 31;
    const int warp = tid >> 5;
    const int warpM = warp >> 1;   // 0..3 -> *32 rows
    const int warpN = warp & 1;    // 0..1 -> *64 cols

    // ---- load mapping: per stage A = 128 rows x 8 chunks = 1024 chunks (4/thread),
    //      B likewise. row = tid>>3 + 32*i, kq = (tid&7)*4 floats.
    const int rbase = tid >> 3;            // 0..31
    const int kq    = (tid & 7) * 4;       // float offset in k (0..28)
    const float* a_src[4]; int a_bytes[4];
#pragma unroll
    for (int i = 0; i < 4; i++) {
        int row = rbase + 32 * i;
        bool ok = (m0 + row) < Mcur;
        int tok = ok ? (list ? list[m0 + row] : (m0 + row)) : 0;
        a_src[i] = Ap + (size_t)tok * lda + kq;
        a_bytes[i] = ok ? 16 : 0;
    }
    const float* b_src0 = Btp + (size_t)(n0 + rbase) * K + kq;
    const size_t bstep = (size_t)32 * K;   // +32 rows

    const uint32_t dynb = (uint32_t)__cvta_generic_to_shared(tg_dyn);
    uint32_t a_d[4], b_d[4];
#pragma unroll
    for (int i = 0; i < 4; i++) {
        a_d[i] = (uint32_t)((rbase + 32 * i) * TS + kq) * 4;
        b_d[i] = (uint32_t)(A_FLOATS + (rbase + 32 * i) * TS + kq) * 4;
    }

    // ---- ldmatrix per-lane offsets
    const int lmA_r = (lane & 7) + ((lane >> 3) & 1) * 8;
    const int lmA_c = ((lane >> 4) & 1) * 4;
    const int lmB_r = (lane & 7) + ((lane >> 4) & 1) * 8;
    const int lmB_c = ((lane >> 3) & 1) * 4;

    float acc[2][8][4];
#pragma unroll
    for (int i = 0; i < 2; i++)
#pragma unroll
        for (int j = 0; j < 8; j++)
#pragma unroll
            for (int r = 0; r < 4; r++) acc[i][j][r] = 0.0f;

    const int T = K / TBK;

    // prefetch tile 0 -> stage 0
#pragma unroll
    for (int i = 0; i < 4; i++) {
        cp_async16(dynb + a_d[i], a_src[i], a_bytes[i]);
        cp_async16(dynb + b_d[i], b_src0 + (size_t)i * bstep, 16);
    }
    cp_commit();

    for (int t = 0; t < T; t++) {
        cp_wait0();
        __syncthreads();

        if (t + 1 < T) {
            const int k0 = (t + 1) * TBK;
            const uint32_t sb = dynb + ((t + 1) & 1) * STAGE_BYTES;
#pragma unroll
            for (int i = 0; i < 4; i++) {
                cp_async16(sb + a_d[i], a_src[i] + k0, a_bytes[i]);
                cp_async16(sb + b_d[i], b_src0 + (size_t)i * bstep + k0, 16);
            }
            cp_commit();
        }

        const uint32_t abuf = dynb + (t & 1) * STAGE_BYTES;
        const uint32_t bbuf = abuf + A_FLOATS * 4;
#pragma unroll
        for (int kk = 0; kk < TBK; kk += 8) {
            uint32_t bfrag[8][2];
#pragma unroll
            for (int j = 0; j < 4; j++) {
                uint32_t addr = bbuf + ((warpN * 64 + j * 16 + lmB_r) * TS + kk + lmB_c) * 4;
                uint32_t r4[4];
                ldsm_x4(r4, addr);
                bfrag[2 * j][0] = r4[0]; bfrag[2 * j][1] = r4[1];
                bfrag[2 * j + 1][0] = r4[2]; bfrag[2 * j + 1][1] = r4[3];
            }
#pragma unroll
            for (int mi = 0; mi < 2; mi++) {
                uint32_t afrag[4];
                uint32_t addr = abuf + ((warpM * 32 + mi * 16 + lmA_r) * TS + kk + lmA_c) * 4;
                ldsm_x4(afrag, addr);
#pragma unroll
                for (int ni = 0; ni < 8; ni++)
                    mma_tf32(acc[mi][ni], afrag, bfrag[ni]);
            }
        }
        __syncthreads();
    }

    const bool even_e = ((e & 1) == 0);
#pragma unroll
    for (int mi = 0; mi < 2; mi++) {
        int mbase = m0 + warpM * 32 + mi * 16 + (lane >> 2);
#pragma unroll
        for (int ni = 0; ni < 8; ni++) {
            int n = n0 + warpN * 64 + ni * 8 + 2 * (lane & 3);
            float bn0 = biasp[n], bn1 = biasp[n + 1];
            if (mbase < Mcur) {
                float v0 = acc[mi][ni][0] + bn0;
                float v1 = acc[mi][ni][1] + bn1;
                if (act_sel == 1) {
                    v0 = even_e ? gelu_exact(v0) : silu(v0);
                    v1 = even_e ? gelu_exact(v1) : silu(v1);
                    v0 = rna_tf32(v0); v1 = rna_tf32(v1);
                }
                *(float2*)&Cp[(size_t)mbase * Nn + n] = make_float2(v0, v1);
            }
            if (mbase + 8 < Mcur) {
                float v2 = acc[mi][ni][2] + bn0;
                float v3 = acc[mi][ni][3] + bn1;
                if (act_sel == 1) {
                    v2 = even_e ? gelu_exact(v2) : silu(v2);
                    v3 = even_e ? gelu_exact(v3) : silu(v3);
                    v2 = rna_tf32(v2); v3 = rna_tf32(v3);
                }
                *(float2*)&Cp[(size_t)(mbase + 8) * Nn + n] = make_float2(v2, v3);
            }
        }
    }
}

// ---------------- LayerNorm + exact GELU ----------------
__global__ __launch_bounds__(256) void ln_gelu_kernel(
    const float* __restrict__ ln_g, const float* __restrict__ ln_b)
{
    const int n = blockIdx.x;
    float* row = g_h + (size_t)n * HDIM;
    const int t = threadIdx.x;
    __shared__ float red[256];

    float v0 = row[t];
    float v1 = row[t + 256];
    red[t] = v0 + v1;
    __syncthreads();
    for (int s = 128; s > 0; s >>= 1) {
        if (t < s) red[t] += red[t + s];
        __syncthreads();
    }
    float mean = red[0] * (1.0f / HDIM);
    __syncthreads();

    float d0 = v0 - mean, d1 = v1 - mean;
    red[t] = d0 * d0 + d1 * d1;
    __syncthreads();
    for (int s = 128; s > 0; s >>= 1) {
        if (t < s) red[t] += red[t + s];
        __syncthreads();
    }
    float var = red[0] * (1.0f / HDIM);
    float inv = rsqrtf(var + LN_EPS);

    float o0 = d0 * inv * ln_g[t] + ln_b[t];
    float o1 = d1 * inv * ln_g[t + 256] + ln_b[t + 256];
    row[t]       = gelu_exact(o0);
    row[t + 256] = gelu_exact(o1);
}

// ---------------- router stage 2 (shuffle-reduced) ----------------
__global__ __launch_bounds__(128) void router2_kernel(
    const float* __restrict__ r2w, const float* __restrict__ r2b,
    const float* __restrict__ temp, const float* __restrict__ rbias)
{
    const int n = blockIdx.x;
    const int t = threadIdx.x;
    const int lane = t & 31, warp = t >> 5;
    const float* row = g_h + (size_t)n * HDIM;

    float acc[EEXP];
#pragma unroll
    for (int e = 0; e < EEXP; e++) acc[e] = 0.0f;
#pragma unroll
    for (int kk = 0; kk < HDIM / 128; kk++) {
        int k = t + kk * 128;
        float hv = row[k];
#pragma unroll
        for (int e = 0; e < EEXP; e++)
            acc[e] = fmaf(hv, r2w[k * EEXP + e], acc[e]);
    }
#pragma unroll
    for (int e = 0; e < EEXP; e++)
#pragma unroll
        for (int o = 16; o > 0; o >>= 1)
            acc[e] += __shfl_xor_sync(0xFFFFFFFF, acc[e], o);

    __shared__ float red[EEXP][4];
    if (lane == 0)
#pragma unroll
        for (int e = 0; e < EEXP; e++) red[e][warp] = acc[e];
    __syncthreads();

    if (t == 0) {
        float logits[EEXP];
        float tinv = 1.0f / temp[0];
#pragma unroll
        for (int e = 0; e < EEXP; e++)
            logits[e] = (red[e][0] + red[e][1] + red[e][2] + red[e][3] + r2b[e]) * tinv + rbias[e];

        float mx = logits[0];
#pragma unroll
        for (int e = 1; e < EEXP; e++) mx = fmaxf(mx, logits[e]);
        float p[EEXP], den = 0.0f;
#pragma unroll
        for (int e = 0; e < EEXP; e++) { p[e] = expf(logits[e] - mx); den += p[e]; }
        float inv = 1.0f / den;
#pragma unroll
        for (int e = 0; e < EEXP; e++) p[e] *= inv;

        int i0 = 0; float v0 = p[0];
#pragma unroll
        for (int e = 1; e < EEXP; e++) if (p[e] > v0) { v0 = p[e]; i0 = e; }
        int i1 = -1; float v1 = -1.0f;
#pragma unroll
        for (int e = 0; e < EEXP; e++) if (e != i0 && p[e] > v1) { v1 = p[e]; i1 = e; }

        int s0 = atomicAdd(&g_counts[i0], 1);
        int s1 = atomicAdd(&g_counts[i1], 1);
        g_lists[(size_t)i0 * NTOK + s0] = n;
        g_lists[(size_t)i1 * NTOK + s1] = n;
        g_as_e[2 * n] = i0; g_as_e[2 * n + 1] = i1;
        g_as_s[2 * n] = s0; g_as_s[2 * n + 1] = s1;
        g_as_w[2 * n] = v0; g_as_w[2 * n + 1] = v1;
    }
}

// ---------------- combine ----------------
__global__ __launch_bounds__(256) void combine_kernel(float* __restrict__ out)
{
    const int n = blockIdx.x;
    const int t = threadIdx.x;
    const int e0 = g_as_e[2 * n],   e1 = g_as_e[2 * n + 1];
    const int s0 = g_as_s[2 * n],   s1 = g_as_s[2 * n + 1];
    const float w0 = g_as_w[2 * n], w1 = g_as_w[2 * n + 1];
    const float4* y0 = (const float4*)(g_y + ((size_t)e0 * NTOK + s0) * DDIM);
    const float4* y1 = (const float4*)(g_y + ((size_t)e1 * NTOK + s1) * DDIM);
    float4* o = (float4*)(out + (size_t)n * DDIM);
    for (int d = t; d < DDIM / 4; d += 256) {
        float4 a = y0[d], b = y1[d];
        o[d] = make_float4(w0 * a.x + w1 * b.x, w0 * a.y + w1 * b.y,
                           w0 * a.z + w1 * b.z, w0 * a.w + w1 * b.w);
    }
}

// ---------------- launch ----------------
extern "C" void kernel_launch(void* const* d_in, const int* in_sizes, int n_in,
                              void* d_out, int out_size)
{
    const float* x      = (const float*)d_in[0];
    const float* r1_w   = (const float*)d_in[1];
    const float* r1_b   = (const float*)d_in[2];
    const float* ln_g   = (const float*)d_in[3];
    const float* ln_b   = (const float*)d_in[4];
    const float* r2_w   = (const float*)d_in[5];
    const float* r2_b   = (const float*)d_in[6];
    const float* temp   = (const float*)d_in[7];
    const float* rbias  = (const float*)d_in[8];
    const float* W1     = (const float*)d_in[9];
    const float* b1     = (const float*)d_in[10];
    const float* W2     = (const float*)d_in[11];
    const float* b2     = (const float*)d_in[12];
    float* out = (float*)d_out;

    void *p_h, *p_xr, *p_r1wt, *p_w1t, *p_w2t, *p_lists, *p_counts, *p_act, *p_y;
    cudaGetSymbolAddress(&p_h, g_h);
    cudaGetSymbolAddress(&p_xr, g_xr);
    cudaGetSymbolAddress(&p_r1wt, g_r1wt);
    cudaGetSymbolAddress(&p_w1t, g_w1t);
    cudaGetSymbolAddress(&p_w2t, g_w2t);
    cudaGetSymbolAddress(&p_lists, g_lists);
    cudaGetSymbolAddress(&p_counts, g_counts);
    cudaGetSymbolAddress(&p_act, g_act);
    cudaGetSymbolAddress(&p_y, g_y);

    cudaFuncSetAttribute(tgemm_kernel, cudaFuncAttributeMaxDynamicSharedMemorySize, TG_SMEM);

    reset_kernel<<<1, 32>>>();

    // prep: round x; transpose+round weights to [N][K]
    round_kernel<<<(NTOK * DDIM) / 1024, 256>>>(x, (float*)p_xr);
    {
        dim3 b(256);
        transpose_rna_kernel<<<dim3(HDIM / 32, DDIM / 32, 1), b>>>(r1_w, (float*)p_r1wt, DDIM, HDIM);
        transpose_rna_kernel<<<dim3(FDIM / 32, DDIM / 32, EEXP), b>>>(W1, (float*)p_w1t, DDIM, FDIM);
        transpose_rna_kernel<<<dim3(DDIM / 32, FDIM / 32, EEXP), b>>>(W2, (float*)p_w2t, FDIM, DDIM);
    }

    // Router GEMM1 (tf32 tensor): h = x @ r1_w + r1_b
    {
        dim3 grid(NTOK / TBM, 1, HDIM / TBN);
        tgemm_kernel<<<grid, 256, TG_SMEM>>>((const float*)p_xr, (const float*)p_r1wt, r1_b,
                                             (float*)p_h, nullptr, nullptr,
                                             NTOK, DDIM, HDIM, DDIM, 0, 0);
    }

    ln_gelu_kernel<<<NTOK, 256>>>(ln_g, ln_b);
    router2_kernel<<<NTOK, 128>>>(r2_w, r2_b, temp, rbias);

    // Expert GEMM1: act = rna(actfn(x[gather] @ W1[e] + b1[e]))
    {
        dim3 grid(NTOK / TBM, EEXP, FDIM / TBN);
        tgemm_kernel<<<grid, 256, TG_SMEM>>>((const float*)p_xr, (const float*)p_w1t, b1,
                                             (float*)p_act, (const int*)p_lists, (const int*)p_counts,
                                             NTOK, DDIM, FDIM, DDIM, 0, 1);
    }

    // Expert GEMM2: y = act @ W2[e] + b2[e]
    {
        dim3 grid(NTOK / TBM, EEXP, DDIM / TBN);
        tgemm_kernel<<<grid, 256, TG_SMEM>>>((const float*)p_act, (const float*)p_w2t, b2,
                                             (float*)p_y, nullptr, (const int*)p_counts,
                                             NTOK, FDIM, DDIM, FDIM,
                                             (size_t)NTOK * FDIM, 0);
    }

    combine_kernel<<<NTOK, 256>>>(out);
}

// round 17
// speedup vs baseline: 2.5143x; 1.5808x over previous
#include <cuda_runtime.h>
#include <cuda_fp16.h>
#include <math.h>
#include <cstdint>

#define NTOK 8192
#define DDIM 1024
#define HDIM 512
#define EEXP 6
#define FDIM 1536
#define LN_EPS 1e-5f

// ---------------- scratch (device globals) ----------------
__device__ float  g_h[(size_t)NTOK * HDIM];               // router hidden (fp32)
__device__ __half g_xh[(size_t)NTOK * DDIM];              // fp16 x
__device__ __half g_r1wt[(size_t)HDIM * DDIM];            // r1_w^T fp16 [H][D]
__device__ __half g_w1t[(size_t)EEXP * FDIM * DDIM];      // W1^T fp16   [E][F][D]
__device__ __half g_w2t[(size_t)EEXP * DDIM * FDIM];      // W2^T fp16   [E][D][F]
__device__ int    g_counts[EEXP];
__device__ int    g_lists[(size_t)EEXP * NTOK];
__device__ int    g_as_e[NTOK * 2];
__device__ int    g_as_s[NTOK * 2];
__device__ float  g_as_w[NTOK * 2];
__device__ __half g_act[(size_t)EEXP * NTOK * FDIM];      // fp16 mid activations
__device__ float  g_y[(size_t)EEXP * NTOK * DDIM];        // fp32 expert outputs

__device__ __forceinline__ float gelu_exact(float x) {
    return 0.5f * x * (1.0f + erff(x * 0.70710678118654752440f));
}
__device__ __forceinline__ float silu(float x) {
    return x / (1.0f + expf(-x));
}

__global__ void reset_kernel() {
    if (threadIdx.x < EEXP) g_counts[threadIdx.x] = 0;
}

// fp32 -> fp16 elementwise (4 elems/thread)
__global__ __launch_bounds__(256) void round_h_kernel(
    const float* __restrict__ src, __half2* __restrict__ dst)
{
    size_t i = (size_t)blockIdx.x * 256 + threadIdx.x;
    const float4 v = ((const float4*)src)[i];
    dst[2 * i]     = __floats2half2_rn(v.x, v.y);
    dst[2 * i + 1] = __floats2half2_rn(v.z, v.w);
}

// transpose [R,C] -> [C,R] fp32 -> fp16; batched over z
__global__ __launch_bounds__(256) void transpose_h_kernel(
    const float* __restrict__ src, __half* __restrict__ dst, int R, int C)
{
    __shared__ float tile[32][33];
    const int e = blockIdx.z;
    src += (size_t)e * R * C;
    dst += (size_t)e * R * C;
    const int c0 = blockIdx.x * 32, r0 = blockIdx.y * 32;
    const int tx = threadIdx.x & 31, ty = threadIdx.x >> 5;
#pragma unroll
    for (int i = ty; i < 32; i += 8)
        tile[i][tx] = src[(size_t)(r0 + i) * C + c0 + tx];
    __syncthreads();
#pragma unroll
    for (int i = ty; i < 32; i += 8)
        dst[(size_t)(c0 + i) * R + r0 + tx] = __float2half_rn(tile[tx][i]);
}

// ============================================================================
// FP16 tensor GEMM (mma.m16n8k16): 128x128x32 tiles, 8 warps (4Mx2N), 32x64/warp.
// Proven structure: 256 thr, 2 CTA/SM, 2-stage double buffer, 2 syncs/tile.
// A: [rows][K] fp16 row-major (gather via lists). Bt: [Nn][K] fp16 row-major.
// C output: fp32 (act_sel==0) or fp16 (act_sel==1, with activation).
// ============================================================================
#define TBM 128
#define TBN 128
#define TBK 32
#define TSH 40                                  // halves per row: 20 words, conflict-free
#define A_BYTES (TBM * TSH * 2)                 // 10240
#define STAGE_BYTES (2 * A_BYTES)               // 20480
#define TG_SMEM (2 * STAGE_BYTES)               // 40960

__device__ __forceinline__ void mma_f16(float* c, const uint32_t* a, const uint32_t* b) {
    asm volatile(
        "mma.sync.aligned.m16n8k16.row.col.f32.f16.f16.f32 "
        "{%0,%1,%2,%3}, {%4,%5,%6,%7}, {%8,%9}, {%0,%1,%2,%3};"
        : "+f"(c[0]), "+f"(c[1]), "+f"(c[2]), "+f"(c[3])
        : "r"(a[0]), "r"(a[1]), "r"(a[2]), "r"(a[3]), "r"(b[0]), "r"(b[1]));
}
__device__ __forceinline__ void ldsm_x4(uint32_t* r, uint32_t addr) {
    asm volatile("ldmatrix.sync.aligned.m8n8.x4.shared.b16 {%0,%1,%2,%3}, [%4];"
                 : "=r"(r[0]), "=r"(r[1]), "=r"(r[2]), "=r"(r[3]) : "r"(addr));
}
__device__ __forceinline__ void cp_async16(uint32_t dst_smem, const void* src, int src_bytes) {
    asm volatile("cp.async.cg.shared.global [%0], [%1], 16, %2;"
                 :: "r"(dst_smem), "l"(src), "r"(src_bytes));
}
__device__ __forceinline__ void cp_commit() { asm volatile("cp.async.commit_group;"); }
__device__ __forceinline__ void cp_wait0() { asm volatile("cp.async.wait_group 0;"); }

extern __shared__ __align__(128) char tg_dyn[];

__global__ __launch_bounds__(256, 2) void tgemm_kernel(
    const __half* __restrict__ A, const __half* __restrict__ Bt,
    const float* __restrict__ bias, void* __restrict__ Cv,
    const int* __restrict__ lists, const int* __restrict__ counts,
    int Mfull, int K, int Nn, int lda, size_t a_estride, int act_sel)
{
    const int e = blockIdx.y;
    const int Mcur = counts ? counts[e] : Mfull;
    const int m0 = blockIdx.x * TBM;
    if (m0 >= Mcur) return;
    const int n0 = blockIdx.z * TBN;

    const __half* Ap    = A + (size_t)e * a_estride;
    const __half* Btp   = Bt + (size_t)e * (size_t)K * Nn;
    const float*  biasp = bias + (size_t)e * Nn;
    const int*    list  = lists ? (lists + (size_t)e * Mfull) : nullptr;

    const int tid  = threadIdx.x;
    const int lane = tid & 31;
    const int warp = tid >> 5;
    const int warpM = warp >> 1;   // 0..3 -> *32 rows
    const int warpN = warp & 1;    // 0..1 -> *64 cols

    // ---- load mapping: per stage A = 128 rows x 4 chunks(16B) = 512 chunks,
    //      2/thread: rows r0 and r0+64, k-chunk kc = (tid&3)*8 halves. B same.
    const int r0i = tid >> 2;              // 0..63
    const int kc  = (tid & 3) * 8;         // half offset in k (0..24)
    const bool av0 = (m0 + r0i) < Mcur;
    const bool av1 = (m0 + r0i + 64) < Mcur;
    const int tok0 = av0 ? (list ? list[m0 + r0i] : (m0 + r0i)) : 0;
    const int tok1 = av1 ? (list ? list[m0 + r0i + 64] : (m0 + r0i + 64)) : 0;
    const __half* a_src0 = Ap + (size_t)tok0 * lda + kc;
    const __half* a_src1 = Ap + (size_t)tok1 * lda + kc;
    const int ab0 = av0 ? 16 : 0, ab1 = av1 ? 16 : 0;
    const __half* b_src0 = Btp + (size_t)(n0 + r0i) * K + kc;
    const __half* b_src1 = Btp + (size_t)(n0 + r0i + 64) * K + kc;

    const uint32_t dynb = (uint32_t)__cvta_generic_to_shared(tg_dyn);
    const uint32_t a_d0 = (uint32_t)(r0i * TSH + kc) * 2;
    const uint32_t a_d1 = (uint32_t)((r0i + 64) * TSH + kc) * 2;
    const uint32_t b_d0 = a_d0 + A_BYTES;
    const uint32_t b_d1 = a_d1 + A_BYTES;

    // ---- ldmatrix per-lane offsets (halves)
    const int lmA_r = (lane & 7) + ((lane >> 3) & 1) * 8;
    const int lmA_k = ((lane >> 4) & 1) * 8;
    const int lmB_r = (lane & 7) + ((lane >> 4) & 1) * 8;
    const int lmB_k = ((lane >> 3) & 1) * 8;

    float acc[2][8][4];
#pragma unroll
    for (int i = 0; i < 2; i++)
#pragma unroll
        for (int j = 0; j < 8; j++)
#pragma unroll
            for (int r = 0; r < 4; r++) acc[i][j][r] = 0.0f;

    const int T = K / TBK;

    // prefetch tile 0 -> stage 0
    cp_async16(dynb + a_d0, a_src0, ab0);
    cp_async16(dynb + a_d1, a_src1, ab1);
    cp_async16(dynb + b_d0, b_src0, 16);
    cp_async16(dynb + b_d1, b_src1, 16);
    cp_commit();

    for (int t = 0; t < T; t++) {
        cp_wait0();
        __syncthreads();

        if (t + 1 < T) {
            const int k0 = (t + 1) * TBK;
            const uint32_t sb = dynb + ((t + 1) & 1) * STAGE_BYTES;
            cp_async16(sb + a_d0, a_src0 + k0, ab0);
            cp_async16(sb + a_d1, a_src1 + k0, ab1);
            cp_async16(sb + b_d0, b_src0 + k0, 16);
            cp_async16(sb + b_d1, b_src1 + k0, 16);
            cp_commit();
        }

        const uint32_t abuf = dynb + (t & 1) * STAGE_BYTES;
        const uint32_t bbuf = abuf + A_BYTES;
#pragma unroll
        for (int kk = 0; kk < TBK; kk += 16) {
            uint32_t bfrag[8][2];
#pragma unroll
            for (int j = 0; j < 4; j++) {
                uint32_t addr = bbuf + ((warpN * 64 + j * 16 + lmB_r) * TSH + kk + lmB_k) * 2;
                uint32_t r4[4];
                ldsm_x4(r4, addr);
                bfrag[2 * j][0] = r4[0]; bfrag[2 * j][1] = r4[1];
                bfrag[2 * j + 1][0] = r4[2]; bfrag[2 * j + 1][1] = r4[3];
            }
#pragma unroll
            for (int mi = 0; mi < 2; mi++) {
                uint32_t afrag[4];
                uint32_t addr = abuf + ((warpM * 32 + mi * 16 + lmA_r) * TSH + kk + lmA_k) * 2;
                ldsm_x4(afrag, addr);
#pragma unroll
                for (int ni = 0; ni < 8; ni++)
                    mma_f16(acc[mi][ni], afrag, bfrag[ni]);
            }
        }
        __syncthreads();
    }

    const bool even_e = ((e & 1) == 0);
#pragma unroll
    for (int mi = 0; mi < 2; mi++) {
        int mbase = m0 + warpM * 32 + mi * 16 + (lane >> 2);
#pragma unroll
        for (int ni = 0; ni < 8; ni++) {
            int n = n0 + warpN * 64 + ni * 8 + 2 * (lane & 3);
            float bn0 = biasp[n], bn1 = biasp[n + 1];
            if (act_sel == 1) {
                __half* Cp = (__half*)Cv + (size_t)e * (size_t)Mfull * Nn;
                if (mbase < Mcur) {
                    float v0 = acc[mi][ni][0] + bn0;
                    float v1 = acc[mi][ni][1] + bn1;
                    v0 = even_e ? gelu_exact(v0) : silu(v0);
                    v1 = even_e ? gelu_exact(v1) : silu(v1);
                    *(__half2*)&Cp[(size_t)mbase * Nn + n] = __floats2half2_rn(v0, v1);
                }
                if (mbase + 8 < Mcur) {
                    float v2 = acc[mi][ni][2] + bn0;
                    float v3 = acc[mi][ni][3] + bn1;
                    v2 = even_e ? gelu_exact(v2) : silu(v2);
                    v3 = even_e ? gelu_exact(v3) : silu(v3);
                    *(__half2*)&Cp[(size_t)(mbase + 8) * Nn + n] = __floats2half2_rn(v2, v3);
                }
            } else {
                float* Cp = (float*)Cv + (size_t)e * (size_t)Mfull * Nn;
                if (mbase < Mcur) {
                    *(float2*)&Cp[(size_t)mbase * Nn + n] =
                        make_float2(acc[mi][ni][0] + bn0, acc[mi][ni][1] + bn1);
                }
                if (mbase + 8 < Mcur) {
                    *(float2*)&Cp[(size_t)(mbase + 8) * Nn + n] =
                        make_float2(acc[mi][ni][2] + bn0, acc[mi][ni][3] + bn1);
                }
            }
        }
    }
}

// ---------------- LayerNorm + exact GELU ----------------
__global__ __launch_bounds__(256) void ln_gelu_kernel(
    const float* __restrict__ ln_g, const float* __restrict__ ln_b)
{
    const int n = blockIdx.x;
    float* row = g_h + (size_t)n * HDIM;
    const int t = threadIdx.x;
    __shared__ float red[256];

    float v0 = row[t];
    float v1 = row[t + 256];
    red[t] = v0 + v1;
    __syncthreads();
    for (int s = 128; s > 0; s >>= 1) {
        if (t < s) red[t] += red[t + s];
        __syncthreads();
    }
    float mean = red[0] * (1.0f / HDIM);
    __syncthreads();

    float d0 = v0 - mean, d1 = v1 - mean;
    red[t] = d0 * d0 + d1 * d1;
    __syncthreads();
    for (int s = 128; s > 0; s >>= 1) {
        if (t < s) red[t] += red[t + s];
        __syncthreads();
    }
    float var = red[0] * (1.0f / HDIM);
    float inv = rsqrtf(var + LN_EPS);

    float o0 = d0 * inv * ln_g[t] + ln_b[t];
    float o1 = d1 * inv * ln_g[t + 256] + ln_b[t + 256];
    row[t]       = gelu_exact(o0);
    row[t + 256] = gelu_exact(o1);
}

// ---------------- router stage 2 (shuffle-reduced) ----------------
__global__ __launch_bounds__(128) void router2_kernel(
    const float* __restrict__ r2w, const float* __restrict__ r2b,
    const float* __restrict__ temp, const float* __restrict__ rbias)
{
    const int n = blockIdx.x;
    const int t = threadIdx.x;
    const int lane = t & 31, warp = t >> 5;
    const float* row = g_h + (size_t)n * HDIM;

    float acc[EEXP];
#pragma unroll
    for (int e = 0; e < EEXP; e++) acc[e] = 0.0f;
#pragma unroll
    for (int kk = 0; kk < HDIM / 128; kk++) {
        int k = t + kk * 128;
        float hv = row[k];
#pragma unroll
        for (int e = 0; e < EEXP; e++)
            acc[e] = fmaf(hv, r2w[k * EEXP + e], acc[e]);
    }
#pragma unroll
    for (int e = 0; e < EEXP; e++)
#pragma unroll
        for (int o = 16; o > 0; o >>= 1)
            acc[e] += __shfl_xor_sync(0xFFFFFFFF, acc[e], o);

    __shared__ float red[EEXP][4];
    if (lane == 0)
#pragma unroll
        for (int e = 0; e < EEXP; e++) red[e][warp] = acc[e];
    __syncthreads();

    if (t == 0) {
        float logits[EEXP];
        float tinv = 1.0f / temp[0];
#pragma unroll
        for (int e = 0; e < EEXP; e++)
            logits[e] = (red[e][0] + red[e][1] + red[e][2] + red[e][3] + r2b[e]) * tinv + rbias[e];

        float mx = logits[0];
#pragma unroll
        for (int e = 1; e < EEXP; e++) mx = fmaxf(mx, logits[e]);
        float p[EEXP], den = 0.0f;
#pragma unroll
        for (int e = 0; e < EEXP; e++) { p[e] = expf(logits[e] - mx); den += p[e]; }
        float inv = 1.0f / den;
#pragma unroll
        for (int e = 0; e < EEXP; e++) p[e] *= inv;

        int i0 = 0; float v0 = p[0];
#pragma unroll
        for (int e = 1; e < EEXP; e++) if (p[e] > v0) { v0 = p[e]; i0 = e; }
        int i1 = -1; float v1 = -1.0f;
#pragma unroll
        for (int e = 0; e < EEXP; e++) if (e != i0 && p[e] > v1) { v1 = p[e]; i1 = e; }

        int s0 = atomicAdd(&g_counts[i0], 1);
        int s1 = atomicAdd(&g_counts[i1], 1);
        g_lists[(size_t)i0 * NTOK + s0] = n;
        g_lists[(size_t)i1 * NTOK + s1] = n;
        g_as_e[2 * n] = i0; g_as_e[2 * n + 1] = i1;
        g_as_s[2 * n] = s0; g_as_s[2 * n + 1] = s1;
        g_as_w[2 * n] = v0; g_as_w[2 * n + 1] = v1;
    }
}

// ---------------- combine ----------------
__global__ __launch_bounds__(256) void combine_kernel(float* __restrict__ out)
{
    const int n = blockIdx.x;
    const int t = threadIdx.x;
    const int e0 = g_as_e[2 * n],   e1 = g_as_e[2 * n + 1];
    const int s0 = g_as_s[2 * n],   s1 = g_as_s[2 * n + 1];
    const float w0 = g_as_w[2 * n], w1 = g_as_w[2 * n + 1];
    const float4* y0 = (const float4*)(g_y + ((size_t)e0 * NTOK + s0) * DDIM);
    const float4* y1 = (const float4*)(g_y + ((size_t)e1 * NTOK + s1) * DDIM);
    float4* o = (float4*)(out + (size_t)n * DDIM);
    for (int d = t; d < DDIM / 4; d += 256) {
        float4 a = y0[d], b = y1[d];
        o[d] = make_float4(w0 * a.x + w1 * b.x, w0 * a.y + w1 * b.y,
                           w0 * a.z + w1 * b.z, w0 * a.w + w1 * b.w);
    }
}

// ---------------- launch ----------------
extern "C" void kernel_launch(void* const* d_in, const int* in_sizes, int n_in,
                              void* d_out, int out_size)
{
    const float* x      = (const float*)d_in[0];
    const float* r1_w   = (const float*)d_in[1];
    const float* r1_b   = (const float*)d_in[2];
    const float* ln_g   = (const float*)d_in[3];
    const float* ln_b   = (const float*)d_in[4];
    const float* r2_w   = (const float*)d_in[5];
    const float* r2_b   = (const float*)d_in[6];
    const float* temp   = (const float*)d_in[7];
    const float* rbias  = (const float*)d_in[8];
    const float* W1     = (const float*)d_in[9];
    const float* b1     = (const float*)d_in[10];
    const float* W2     = (const float*)d_in[11];
    const float* b2     = (const float*)d_in[12];
    float* out = (float*)d_out;

    void *p_h, *p_xh, *p_r1wt, *p_w1t, *p_w2t, *p_lists, *p_counts, *p_act, *p_y;
    cudaGetSymbolAddress(&p_h, g_h);
    cudaGetSymbolAddress(&p_xh, g_xh);
    cudaGetSymbolAddress(&p_r1wt, g_r1wt);
    cudaGetSymbolAddress(&p_w1t, g_w1t);
    cudaGetSymbolAddress(&p_w2t, g_w2t);
    cudaGetSymbolAddress(&p_lists, g_lists);
    cudaGetSymbolAddress(&p_counts, g_counts);
    cudaGetSymbolAddress(&p_act, g_act);
    cudaGetSymbolAddress(&p_y, g_y);

    cudaFuncSetAttribute(tgemm_kernel, cudaFuncAttributeMaxDynamicSharedMemorySize, TG_SMEM);

    reset_kernel<<<1, 32>>>();

    // prep: fp16 x; transpose+fp16 weights to [N][K]
    round_h_kernel<<<(NTOK * DDIM) / 1024, 256>>>(x, (__half2*)p_xh);
    {
        dim3 b(256);
        transpose_h_kernel<<<dim3(HDIM / 32, DDIM / 32, 1), b>>>(r1_w, (__half*)p_r1wt, DDIM, HDIM);
        transpose_h_kernel<<<dim3(FDIM / 32, DDIM / 32, EEXP), b>>>(W1, (__half*)p_w1t, DDIM, FDIM);
        transpose_h_kernel<<<dim3(DDIM / 32, FDIM / 32, EEXP), b>>>(W2, (__half*)p_w2t, FDIM, DDIM);
    }

    // Router GEMM1 (fp16 tensor): h = x @ r1_w + r1_b  (fp32 out)
    {
        dim3 grid(NTOK / TBM, 1, HDIM / TBN);
        tgemm_kernel<<<grid, 256, TG_SMEM>>>((const __half*)p_xh, (const __half*)p_r1wt, r1_b,
                                             p_h, nullptr, nullptr,
                                             NTOK, DDIM, HDIM, DDIM, 0, 0);
    }

    ln_gelu_kernel<<<NTOK, 256>>>(ln_g, ln_b);
    router2_kernel<<<NTOK, 128>>>(r2_w, r2_b, temp, rbias);

    // Expert GEMM1: act(fp16) = actfn(x[gather] @ W1[e] + b1[e])
    {
        dim3 grid(NTOK / TBM, EEXP, FDIM / TBN);
        tgemm_kernel<<<grid, 256, TG_SMEM>>>((const __half*)p_xh, (const __half*)p_w1t, b1,
                                             p_act, (const int*)p_lists, (const int*)p_counts,
                                             NTOK, DDIM, FDIM, DDIM, 0, 1);
    }

    // Expert GEMM2: y(fp32) = act @ W2[e] + b2[e]
    {
        dim3 grid(NTOK / TBM, EEXP, DDIM / TBN);
        tgemm_kernel<<<grid, 256, TG_SMEM>>>((const __half*)p_act, (const __half*)p_w2t, b2,
                                             p_y, nullptr, (const int*)p_counts,
                                             NTOK, FDIM, DDIM, FDIM,
                                             (size_t)NTOK * FDIM, 0);
    }

    combine_kernel<<<NTOK, 256>>>(out);
}